// round 1
// baseline (speedup 1.0000x reference)
#include <cuda_runtime.h>
#include <math.h>

#define T 4096
#define D 1024
#define HDIM 4096
#define E 8

#define BM 128
#define BN 128
#define BK 8

// ---------------- scratch (device globals; no allocation allowed) ----------------
__device__ int   g_counts[E];
__device__ int   g_offsets[E];
__device__ int   g_cursor[E];
__device__ int   g_tok_e[2 * T];        // per token: 2 expert ids
__device__ float g_tok_w[2 * T];        // per token: 2 gate weights
__device__ int   g_tok_pair[2 * T];     // per token: pair slot indices
__device__ int   g_pair_token[2 * T];   // per pair slot: token id
__device__ float g_probs[T * E];        // full softmax probs (for aux)
__device__ float g_h[(size_t)2 * T * HDIM];   // GEMM1 output (gelu'd), 128 MB
__device__ float g_opair[(size_t)2 * T * D];  // GEMM2 output per pair, 32 MB

// ---------------- helpers ----------------
__device__ __forceinline__ float gelu_tanh(float v) {
    // JAX default gelu (approximate=True)
    float c = v + 0.044715f * v * v * v;
    return 0.5f * v * (1.0f + tanhf(0.7978845608028654f * c));
}

// ---------------- kernels ----------------
__global__ void init_kernel() {
    if (threadIdx.x < E) g_counts[threadIdx.x] = 0;
}

__global__ __launch_bounds__(256) void router_kernel(const float* __restrict__ x,
                                                     const float* __restrict__ wg) {
    __shared__ float ws[E * D];
    for (int i = threadIdx.x; i < E * D; i += 256) ws[i] = wg[i];
    __syncthreads();

    int warp = threadIdx.x >> 5, lane = threadIdx.x & 31;
    int t = blockIdx.x * 8 + warp;

    float p[E];
#pragma unroll
    for (int e = 0; e < E; e++) p[e] = 0.0f;

    const float* xr = x + (size_t)t * D;
    for (int i = lane; i < D; i += 32) {
        float xv = xr[i];
#pragma unroll
        for (int e = 0; e < E; e++) p[e] += xv * ws[e * D + i];
    }
#pragma unroll
    for (int e = 0; e < E; e++) {
#pragma unroll
        for (int off = 16; off > 0; off >>= 1)
            p[e] += __shfl_down_sync(0xffffffffu, p[e], off);
    }
    if (lane == 0) {
        // full softmax probs (TEMPERATURE = 1)
        float mx = p[0];
#pragma unroll
        for (int e = 1; e < E; e++) mx = fmaxf(mx, p[e]);
        float ex[E];
        float s = 0.0f;
#pragma unroll
        for (int e = 0; e < E; e++) { ex[e] = expf(p[e] - mx); s += ex[e]; }
        float inv = 1.0f / s;
#pragma unroll
        for (int e = 0; e < E; e++) g_probs[t * E + e] = ex[e] * inv;

        // top-2 (strict > keeps lowest index on ties, matching lax.top_k)
        int i0 = 0;
#pragma unroll
        for (int e = 1; e < E; e++) if (p[e] > p[i0]) i0 = e;
        int i1 = (i0 == 0) ? 1 : 0;
#pragma unroll
        for (int e = 0; e < E; e++) if (e != i0 && p[e] > p[i1]) i1 = e;

        float w0 = 1.0f / (1.0f + expf(p[i1] - p[i0]));
        float w1 = 1.0f - w0;
        g_tok_e[2 * t]     = i0;
        g_tok_e[2 * t + 1] = i1;
        g_tok_w[2 * t]     = w0;
        g_tok_w[2 * t + 1] = w1;
        atomicAdd(&g_counts[i0], 1);
        atomicAdd(&g_counts[i1], 1);
    }
}

// Single block: deterministic aux reduction, offsets scan, cursor reset.
__global__ __launch_bounds__(256) void setup_kernel(float* __restrict__ d_out, int out_size) {
    int tid = threadIdx.x;
    float gs[E], ps[E];
#pragma unroll
    for (int e = 0; e < E; e++) { gs[e] = 0.0f; ps[e] = 0.0f; }

    for (int t = tid; t < T; t += 256) {
        gs[g_tok_e[2 * t]]     += g_tok_w[2 * t];
        gs[g_tok_e[2 * t + 1]] += g_tok_w[2 * t + 1];
#pragma unroll
        for (int e = 0; e < E; e++) ps[e] += g_probs[t * E + e];
    }

    __shared__ float red[256];
    __shared__ float gsum[E], psum[E];
    for (int e = 0; e < E; e++) {
        red[tid] = gs[e];
        __syncthreads();
        for (int s = 128; s > 0; s >>= 1) {
            if (tid < s) red[tid] += red[tid + s];
            __syncthreads();
        }
        if (tid == 0) gsum[e] = red[0];
        __syncthreads();
    }
    for (int e = 0; e < E; e++) {
        red[tid] = ps[e];
        __syncthreads();
        for (int s = 128; s > 0; s >>= 1) {
            if (tid < s) red[tid] += red[tid + s];
            __syncthreads();
        }
        if (tid == 0) psum[e] = red[0];
        __syncthreads();
    }

    if (tid == 0) {
        float aux = 0.0f;
        for (int e = 0; e < E; e++)
            aux += (gsum[e] / (float)T) * (psum[e] / (float)T);
        aux *= (float)E;
        if (out_size > T * D) d_out[T * D] = aux;

        int off = 0;
        for (int e = 0; e < E; e++) {
            g_offsets[e] = off;
            off += g_counts[e];
            g_cursor[e] = 0;
        }
    }
}

__global__ __launch_bounds__(256) void scatter_kernel() {
    int t = blockIdx.x * 256 + threadIdx.x;
    if (t >= T) return;
#pragma unroll
    for (int k = 0; k < 2; k++) {
        int e = g_tok_e[2 * t + k];
        int p = g_offsets[e] + atomicAdd(&g_cursor[e], 1);
        g_pair_token[p] = t;
        g_tok_pair[2 * t + k] = p;
    }
}

// GEMM1: for expert e, rows = its token pairs (gathered x rows), B = W1[e] [D,H].
// Epilogue: gelu(acc + b1[e]) -> g_h.
__global__ __launch_bounds__(256) void gemm1_kernel(const float* __restrict__ x,
                                                    const float* __restrict__ W1,
                                                    const float* __restrict__ b1) {
    int e = blockIdx.z;
    int cnt = g_counts[e];
    int m0 = blockIdx.y * BM;
    if (m0 >= cnt) return;
    int base = g_offsets[e];
    int n0 = blockIdx.x * BN;
    const float* Bmat = W1 + (size_t)e * D * HDIM;

    __shared__ float As[BK][BM];
    __shared__ float Bs[BK][BN];
    __shared__ int rowtok[BM];

    int tid = threadIdx.x;
    for (int i = tid; i < BM; i += 256) {
        int m = m0 + i;
        rowtok[i] = g_pair_token[base + (m < cnt ? m : 0)];
    }
    __syncthreads();

    int tx = tid & 15, ty = tid >> 4;
    int a_m = tid >> 1;
    int a_k = (tid & 1) * 4;
    int b_k = tid >> 5;
    int b_n = (tid & 31) * 4;
    size_t a_row = (size_t)rowtok[a_m] * D;

    float acc[8][8];
#pragma unroll
    for (int i = 0; i < 8; i++)
#pragma unroll
        for (int j = 0; j < 8; j++) acc[i][j] = 0.0f;

    float4 av = *(const float4*)(x + a_row + a_k);
    float4 bv = *(const float4*)(Bmat + (size_t)b_k * HDIM + n0 + b_n);

    for (int k0 = 0; k0 < D; k0 += BK) {
        As[a_k + 0][a_m] = av.x;
        As[a_k + 1][a_m] = av.y;
        As[a_k + 2][a_m] = av.z;
        As[a_k + 3][a_m] = av.w;
        *(float4*)&Bs[b_k][b_n] = bv;
        __syncthreads();

        float4 av2 = av, bv2 = bv;
        int k1 = k0 + BK;
        if (k1 < D) {
            av2 = *(const float4*)(x + a_row + k1 + a_k);
            bv2 = *(const float4*)(Bmat + (size_t)(k1 + b_k) * HDIM + n0 + b_n);
        }

#pragma unroll
        for (int k = 0; k < BK; k++) {
            float a[8], b[8];
            *(float4*)(a)     = *(const float4*)&As[k][ty * 8];
            *(float4*)(a + 4) = *(const float4*)&As[k][ty * 8 + 4];
            *(float4*)(b)     = *(const float4*)&Bs[k][tx * 8];
            *(float4*)(b + 4) = *(const float4*)&Bs[k][tx * 8 + 4];
#pragma unroll
            for (int i = 0; i < 8; i++)
#pragma unroll
                for (int j = 0; j < 8; j++) acc[i][j] += a[i] * b[j];
        }
        __syncthreads();
        av = av2;
        bv = bv2;
    }

#pragma unroll
    for (int i = 0; i < 8; i++) {
        int m = m0 + ty * 8 + i;
        if (m >= cnt) continue;
        size_t hbase = (size_t)(base + m) * HDIM + n0 + tx * 8;
        const float* b1p = b1 + e * HDIM + n0 + tx * 8;
#pragma unroll
        for (int j = 0; j < 8; j++) {
            float v = acc[i][j] + b1p[j];
            g_h[hbase + j] = gelu_tanh(v);
        }
    }
}

// GEMM2: A = g_h rows of expert e (contiguous), B = W2[e] [H,D]. Output -> g_opair.
__global__ __launch_bounds__(256) void gemm2_kernel(const float* __restrict__ W2) {
    int e = blockIdx.z;
    int cnt = g_counts[e];
    int m0 = blockIdx.y * BM;
    if (m0 >= cnt) return;
    int base = g_offsets[e];
    int n0 = blockIdx.x * BN;
    const float* Bmat = W2 + (size_t)e * HDIM * D;

    __shared__ float As[BK][BM];
    __shared__ float Bs[BK][BN];

    int tid = threadIdx.x;
    int tx = tid & 15, ty = tid >> 4;
    int a_m = tid >> 1;
    int a_k = (tid & 1) * 4;
    int b_k = tid >> 5;
    int b_n = (tid & 31) * 4;

    int am_clamped = (m0 + a_m < cnt) ? (m0 + a_m) : 0;
    size_t a_row = (size_t)(base + am_clamped) * HDIM;

    float acc[8][8];
#pragma unroll
    for (int i = 0; i < 8; i++)
#pragma unroll
        for (int j = 0; j < 8; j++) acc[i][j] = 0.0f;

    float4 av = *(const float4*)(g_h + a_row + a_k);
    float4 bv = *(const float4*)(Bmat + (size_t)b_k * D + n0 + b_n);

    for (int k0 = 0; k0 < HDIM; k0 += BK) {
        As[a_k + 0][a_m] = av.x;
        As[a_k + 1][a_m] = av.y;
        As[a_k + 2][a_m] = av.z;
        As[a_k + 3][a_m] = av.w;
        *(float4*)&Bs[b_k][b_n] = bv;
        __syncthreads();

        float4 av2 = av, bv2 = bv;
        int k1 = k0 + BK;
        if (k1 < HDIM) {
            av2 = *(const float4*)(g_h + a_row + k1 + a_k);
            bv2 = *(const float4*)(Bmat + (size_t)(k1 + b_k) * D + n0 + b_n);
        }

#pragma unroll
        for (int k = 0; k < BK; k++) {
            float a[8], b[8];
            *(float4*)(a)     = *(const float4*)&As[k][ty * 8];
            *(float4*)(a + 4) = *(const float4*)&As[k][ty * 8 + 4];
            *(float4*)(b)     = *(const float4*)&Bs[k][tx * 8];
            *(float4*)(b + 4) = *(const float4*)&Bs[k][tx * 8 + 4];
#pragma unroll
            for (int i = 0; i < 8; i++)
#pragma unroll
                for (int j = 0; j < 8; j++) acc[i][j] += a[i] * b[j];
        }
        __syncthreads();
        av = av2;
        bv = bv2;
    }

#pragma unroll
    for (int i = 0; i < 8; i++) {
        int m = m0 + ty * 8 + i;
        if (m >= cnt) continue;
        size_t obase = (size_t)(base + m) * D + n0 + tx * 8;
#pragma unroll
        for (int j = 0; j < 8; j++) g_opair[obase + j] = acc[i][j];
    }
}

// y[t,d] = w0*(eo0 + b2[e0,d]) + w1*(eo1 + b2[e1,d]); vectorized by float4.
__global__ __launch_bounds__(256) void combine_kernel(const float* __restrict__ b2,
                                                      float* __restrict__ out) {
    int idx4 = blockIdx.x * 256 + threadIdx.x;  // over T*D/4
    int t = idx4 >> 8;        // D/4 = 256 float4 per token
    int d4 = (idx4 & 255) * 4;

    int p0 = g_tok_pair[2 * t], p1 = g_tok_pair[2 * t + 1];
    int e0 = g_tok_e[2 * t],    e1 = g_tok_e[2 * t + 1];
    float w0 = g_tok_w[2 * t],  w1 = g_tok_w[2 * t + 1];

    float4 o0 = *(const float4*)(g_opair + (size_t)p0 * D + d4);
    float4 o1 = *(const float4*)(g_opair + (size_t)p1 * D + d4);
    float4 bb0 = *(const float4*)(b2 + (size_t)e0 * D + d4);
    float4 bb1 = *(const float4*)(b2 + (size_t)e1 * D + d4);

    float4 r;
    r.x = w0 * (o0.x + bb0.x) + w1 * (o1.x + bb1.x);
    r.y = w0 * (o0.y + bb0.y) + w1 * (o1.y + bb1.y);
    r.z = w0 * (o0.z + bb0.z) + w1 * (o1.z + bb1.z);
    r.w = w0 * (o0.w + bb0.w) + w1 * (o1.w + bb1.w);
    *(float4*)(out + (size_t)t * D + d4) = r;
}

// ---------------- launch ----------------
extern "C" void kernel_launch(void* const* d_in, const int* in_sizes, int n_in,
                              void* d_out, int out_size) {
    const float* x  = (const float*)d_in[0];
    const float* wg = (const float*)d_in[1];
    const float* W1 = (const float*)d_in[2];
    const float* b1 = (const float*)d_in[3];
    const float* W2 = (const float*)d_in[4];
    const float* b2 = (const float*)d_in[5];
    float* out = (float*)d_out;

    init_kernel<<<1, 32>>>();
    router_kernel<<<T / 8, 256>>>(x, wg);
    setup_kernel<<<1, 256>>>(out, out_size);
    scatter_kernel<<<T / 256, 256>>>();
    gemm1_kernel<<<dim3(HDIM / BN, T / BM, E), 256>>>(x, W1, b1);
    gemm2_kernel<<<dim3(D / BN, T / BM, E), 256>>>(W2);
    combine_kernel<<<(T * D / 4) / 256, 256>>>(b2, out);
}

// round 3
// speedup vs baseline: 2.9910x; 2.9910x over previous
#include <cuda_runtime.h>
#include <math.h>
#include <stdint.h>

#define T 4096
#define D 1024
#define HDIM 4096
#define E 8
#define BM 128
#define BN 128
#define BK 32
#define STAGES 4
#define STAGE_BYTES 32768   // A 16KB + B 16KB
#define SMEM_DYN (STAGES * STAGE_BYTES)
#define MAXTILES 72

// ---------------- scratch (device globals) ----------------
__device__ int   g_counts[E];
__device__ int   g_offsets[E];
__device__ int   g_cursor[E];
__device__ int   g_tok_e[2 * T];
__device__ float g_tok_w[2 * T];
__device__ int   g_tok_pair[2 * T];
__device__ int   g_pair_token[2 * T];
__device__ float g_probs[T * E];
__device__ int   g_tile_e[MAXTILES];
__device__ int   g_tile_m0[MAXTILES];
__device__ int   g_ntiles;
__device__ float g_xa[(2 * T + 128) * D];                    // gathered+rounded x
__device__ float g_h[(size_t)(2 * T + 128) * HDIM];          // gelu output (tf32-rounded)
__device__ float g_opair[(size_t)2 * T * D];                 // gemm2 out
__device__ float g_w1t[(size_t)E * HDIM * D];                // W1^T rounded: [E][H][D]
__device__ float g_w2t[(size_t)E * D * HDIM];                // W2^T rounded: [E][D][H]

// ---------------- PTX helpers ----------------
__device__ __forceinline__ uint32_t smem_u32(const void* p) {
    uint32_t a;
    asm("{ .reg .u64 t; cvta.to.shared.u64 t, %1; cvt.u32.u64 %0, t; }" : "=r"(a) : "l"(p));
    return a;
}
__device__ __forceinline__ float round_tf32(float f) {
    uint32_t u;
    asm("cvt.rna.tf32.f32 %0, %1;" : "=r"(u) : "f"(f));
    return __uint_as_float(u);
}

#define CP_ASYNC16(saddr, gptr) \
    asm volatile("cp.async.cg.shared.global [%0], [%1], 16;" :: "r"(saddr), "l"(gptr) : "memory")
#define CP_COMMIT() asm volatile("cp.async.commit_group;" ::: "memory")
#define CP_WAIT(n)  asm volatile("cp.async.wait_group %0;" :: "n"(n) : "memory")

#define LDSM_X4(r0, r1, r2, r3, addr) \
    asm volatile("ldmatrix.sync.aligned.m8n8.x4.shared.b16 {%0,%1,%2,%3}, [%4];" \
        : "=r"(r0), "=r"(r1), "=r"(r2), "=r"(r3) : "r"(addr))

#define MMA_TF32(d, a, b0, b1) \
    asm volatile("mma.sync.aligned.m16n8k8.row.col.f32.tf32.tf32.f32 " \
        "{%0,%1,%2,%3}, {%4,%5,%6,%7}, {%8,%9}, {%0,%1,%2,%3};" \
        : "+f"((d)[0]), "+f"((d)[1]), "+f"((d)[2]), "+f"((d)[3]) \
        : "r"((a)[0]), "r"((a)[1]), "r"((a)[2]), "r"((a)[3]), "r"(b0), "r"(b1))

__device__ __forceinline__ uint32_t swz(uint32_t off) {
    return off ^ ((off >> 3) & 0x70);
}

__device__ __forceinline__ float gelu_tanh(float v) {
    float c = v + 0.044715f * v * v * v;
    return 0.5f * v * (1.0f + tanhf(0.7978845608028654f * c));
}

// ---------------- routing kernels ----------------
__global__ void init_kernel() {
    if (threadIdx.x < E) g_counts[threadIdx.x] = 0;
}

__global__ __launch_bounds__(256) void router_kernel(const float* __restrict__ x,
                                                     const float* __restrict__ wg) {
    __shared__ float ws[E * D];
    for (int i = threadIdx.x; i < E * D; i += 256) ws[i] = wg[i];
    __syncthreads();
    int warp = threadIdx.x >> 5, lane = threadIdx.x & 31;
    int t = blockIdx.x * 8 + warp;
    float p[E];
#pragma unroll
    for (int e = 0; e < E; e++) p[e] = 0.0f;
    const float* xr = x + (size_t)t * D;
    for (int i = lane; i < D; i += 32) {
        float xv = xr[i];
#pragma unroll
        for (int e = 0; e < E; e++) p[e] += xv * ws[e * D + i];
    }
#pragma unroll
    for (int e = 0; e < E; e++)
#pragma unroll
        for (int off = 16; off > 0; off >>= 1)
            p[e] += __shfl_down_sync(0xffffffffu, p[e], off);
    if (lane == 0) {
        float mx = p[0];
#pragma unroll
        for (int e = 1; e < E; e++) mx = fmaxf(mx, p[e]);
        float ex[E], s = 0.0f;
#pragma unroll
        for (int e = 0; e < E; e++) { ex[e] = expf(p[e] - mx); s += ex[e]; }
        float inv = 1.0f / s;
#pragma unroll
        for (int e = 0; e < E; e++) g_probs[t * E + e] = ex[e] * inv;
        int i0 = 0;
#pragma unroll
        for (int e = 1; e < E; e++) if (p[e] > p[i0]) i0 = e;
        int i1 = (i0 == 0) ? 1 : 0;
#pragma unroll
        for (int e = 0; e < E; e++) if (e != i0 && p[e] > p[i1]) i1 = e;
        float w0 = 1.0f / (1.0f + expf(p[i1] - p[i0]));
        g_tok_e[2 * t] = i0;  g_tok_e[2 * t + 1] = i1;
        g_tok_w[2 * t] = w0;  g_tok_w[2 * t + 1] = 1.0f - w0;
        atomicAdd(&g_counts[i0], 1);
        atomicAdd(&g_counts[i1], 1);
    }
}

__global__ __launch_bounds__(256) void setup_kernel(float* __restrict__ d_out, int out_size) {
    int tid = threadIdx.x;
    float gs[E], ps[E];
#pragma unroll
    for (int e = 0; e < E; e++) { gs[e] = 0.0f; ps[e] = 0.0f; }
    for (int t = tid; t < T; t += 256) {
        gs[g_tok_e[2 * t]]     += g_tok_w[2 * t];
        gs[g_tok_e[2 * t + 1]] += g_tok_w[2 * t + 1];
#pragma unroll
        for (int e = 0; e < E; e++) ps[e] += g_probs[t * E + e];
    }
    __shared__ float red[256];
    __shared__ float gsum[E], psum[E];
    for (int e = 0; e < E; e++) {
        red[tid] = gs[e]; __syncthreads();
        for (int s = 128; s > 0; s >>= 1) { if (tid < s) red[tid] += red[tid + s]; __syncthreads(); }
        if (tid == 0) gsum[e] = red[0];
        __syncthreads();
    }
    for (int e = 0; e < E; e++) {
        red[tid] = ps[e]; __syncthreads();
        for (int s = 128; s > 0; s >>= 1) { if (tid < s) red[tid] += red[tid + s]; __syncthreads(); }
        if (tid == 0) psum[e] = red[0];
        __syncthreads();
    }
    if (tid == 0) {
        float aux = 0.0f;
        for (int e = 0; e < E; e++) aux += (gsum[e] / (float)T) * (psum[e] / (float)T);
        aux *= (float)E;
        if (out_size > T * D) d_out[T * D] = aux;
        int off = 0, nt = 0;
        for (int e = 0; e < E; e++) {
            g_offsets[e] = off;
            for (int m0 = 0; m0 < g_counts[e]; m0 += BM) { g_tile_e[nt] = e; g_tile_m0[nt] = m0; nt++; }
            off += g_counts[e];
            g_cursor[e] = 0;
        }
        g_ntiles = nt;
    }
}

__global__ __launch_bounds__(256) void scatter_kernel() {
    int t = blockIdx.x * 256 + threadIdx.x;
    if (t >= T) return;
#pragma unroll
    for (int k = 0; k < 2; k++) {
        int e = g_tok_e[2 * t + k];
        int p = g_offsets[e] + atomicAdd(&g_cursor[e], 1);
        g_pair_token[p] = t;
        g_tok_pair[2 * t + k] = p;
    }
}

// gather x rows into pair order, round to tf32 (rna)
__global__ __launch_bounds__(256) void gather_kernel(const float* __restrict__ x) {
    int p = blockIdx.x;
    int tok = g_pair_token[p];
    int c = threadIdx.x * 4;
    float4 v = *(const float4*)(x + (size_t)tok * D + c);
    v.x = round_tf32(v.x); v.y = round_tf32(v.y);
    v.z = round_tf32(v.z); v.w = round_tf32(v.w);
    *(float4*)(g_xa + (size_t)p * D + c) = v;
}

// transpose [K][N] -> [N][K] per expert, with tf32 rna rounding
__global__ __launch_bounds__(256) void transpose_round_kernel(const float* __restrict__ src,
                                                              float* __restrict__ dst,
                                                              int K, int N) {
    __shared__ float s[32][33];
    int e = blockIdx.z;
    src += (size_t)e * K * N;
    dst += (size_t)e * N * K;
    int k0 = blockIdx.y * 32, n0 = blockIdx.x * 32;
    int r = threadIdx.x >> 3;
    int c4 = (threadIdx.x & 7) * 4;
    float4 v = *(const float4*)(src + (size_t)(k0 + r) * N + n0 + c4);
    s[r][c4 + 0] = round_tf32(v.x);
    s[r][c4 + 1] = round_tf32(v.y);
    s[r][c4 + 2] = round_tf32(v.z);
    s[r][c4 + 3] = round_tf32(v.w);
    __syncthreads();
    float4 w;
    w.x = s[c4 + 0][r];
    w.y = s[c4 + 1][r];
    w.z = s[c4 + 2][r];
    w.w = s[c4 + 3][r];
    *(float4*)(dst + (size_t)(n0 + r) * K + k0 + c4) = w;
}

// ---------------- tf32 mma.sync grouped GEMM ----------------
// A: [pairs][KTOT] k-major (gathered). Bt: [E][NTOT][KTOT] k-major (pre-transposed).
// CTA tile 128x128, BK=32, 4-stage cp.async pipeline, 8 warps (2m x 4n), warp tile 64x32.
template<int KTOT, int NTOT, bool GELU>
__global__ __launch_bounds__(256, 1) void mma_gemm_kernel(
    const float* __restrict__ Aall, const float* __restrict__ Bt,
    const float* __restrict__ bias, float* __restrict__ Out)
{
    int ty = blockIdx.y;
    if (ty >= g_ntiles) return;
    int e = g_tile_e[ty];
    int m0 = g_tile_m0[ty];
    int cnt = g_counts[e];
    int base = g_offsets[e];
    int n0 = blockIdx.x * BN;

    extern __shared__ char sm[];
    uint32_t sbase = smem_u32(sm);
    int tid = threadIdx.x;
    int wid = tid >> 5, lane = tid & 31;
    int warp_m = wid & 1, warp_n = wid >> 1;
    int m_base = warp_m * 64, n_base = warp_n * 32;

    const float* Abase = Aall + (size_t)(base + m0) * KTOT;
    const float* Bbase = Bt + ((size_t)e * NTOT + n0) * KTOT;

    // producer chunk mapping (identical for A and B: 128 rows x 128B, 16B chunks)
    int p_row = 0, p_cc = 0;
    {
        // computed per j below
    }

    float acc[4][4][4];
#pragma unroll
    for (int i = 0; i < 4; i++)
#pragma unroll
        for (int j = 0; j < 4; j++)
#pragma unroll
            for (int k = 0; k < 4; k++) acc[i][j][k] = 0.0f;

    const int KITERS = KTOT / BK;

#define LOAD_STAGE(s, it) do { \
        uint32_t a_sm_ = sbase + (uint32_t)(s) * STAGE_BYTES; \
        uint32_t b_sm_ = a_sm_ + 16384; \
        int k0_ = (it) * BK; \
        _Pragma("unroll") \
        for (int j_ = 0; j_ < 4; j_++) { \
            int chunk_ = tid + 256 * j_; \
            int row_ = chunk_ >> 3, cc_ = chunk_ & 7; \
            uint32_t off_ = (uint32_t)(row_ * 128 + cc_ * 16); \
            CP_ASYNC16(a_sm_ + swz(off_), Abase + (size_t)row_ * KTOT + k0_ + cc_ * 4); \
        } \
        _Pragma("unroll") \
        for (int j_ = 0; j_ < 4; j_++) { \
            int chunk_ = tid + 256 * j_; \
            int row_ = chunk_ >> 3, cc_ = chunk_ & 7; \
            uint32_t off_ = (uint32_t)(row_ * 128 + cc_ * 16); \
            CP_ASYNC16(b_sm_ + swz(off_), Bbase + (size_t)row_ * KTOT + k0_ + cc_ * 4); \
        } \
    } while (0)

    // prologue: fill STAGES-1 stages
#pragma unroll
    for (int s = 0; s < STAGES - 1; s++) {
        LOAD_STAGE(s, s);
        CP_COMMIT();
    }

    int lrow = lane & 15;
    uint32_t lkhi = (uint32_t)((lane >> 4) * 16);

    for (int it = 0; it < KITERS; ++it) {
        CP_WAIT(STAGES - 2);
        __syncthreads();

        int nxt = it + STAGES - 1;
        if (nxt < KITERS) LOAD_STAGE(nxt % STAGES, nxt);
        CP_COMMIT();

        uint32_t a_sm = sbase + (uint32_t)(it % STAGES) * STAGE_BYTES;
        uint32_t b_sm = a_sm + 16384;

#pragma unroll
        for (int ks = 0; ks < 4; ks++) {
            uint32_t a[4][4], b[2][4];
#pragma unroll
            for (int mt = 0; mt < 4; mt++) {
                uint32_t off = (uint32_t)((m_base + mt * 16 + lrow) * 128) + ks * 32 + lkhi;
                LDSM_X4(a[mt][0], a[mt][1], a[mt][2], a[mt][3], a_sm + swz(off));
            }
#pragma unroll
            for (int np = 0; np < 2; np++) {
                uint32_t off = (uint32_t)((n_base + np * 16 + lrow) * 128) + ks * 32 + lkhi;
                LDSM_X4(b[np][0], b[np][1], b[np][2], b[np][3], b_sm + swz(off));
            }
#pragma unroll
            for (int mt = 0; mt < 4; mt++)
#pragma unroll
                for (int nt = 0; nt < 4; nt++)
                    MMA_TF32(acc[mt][nt], a[mt], b[nt >> 1][nt & 1], b[nt >> 1][(nt & 1) + 2]);
        }
    }

    // ---- epilogue ----
    int rq = lane >> 2;
    int cq = (lane & 3) * 2;
#pragma unroll
    for (int mt = 0; mt < 4; mt++) {
#pragma unroll
        for (int h = 0; h < 2; h++) {
            int row = m_base + mt * 16 + h * 8 + rq;
            int m = m0 + row;
            if (m >= cnt) continue;
            float* orow = Out + (size_t)(base + m) * NTOT + n0;
#pragma unroll
            for (int nt = 0; nt < 4; nt++) {
                int col = n_base + nt * 8 + cq;
                float v0 = acc[mt][nt][h * 2 + 0];
                float v1 = acc[mt][nt][h * 2 + 1];
                if (GELU) {
                    const float* bp = bias + (size_t)e * NTOT + n0 + col;
                    v0 = round_tf32(gelu_tanh(v0 + bp[0]));
                    v1 = round_tf32(gelu_tanh(v1 + bp[1]));
                }
                float2 st;
                st.x = v0; st.y = v1;
                *(float2*)(orow + col) = st;
            }
        }
    }
#undef LOAD_STAGE
}

// ---------------- combine ----------------
__global__ __launch_bounds__(256) void combine_kernel(const float* __restrict__ b2,
                                                      float* __restrict__ out) {
    int idx4 = blockIdx.x * 256 + threadIdx.x;
    int t = idx4 >> 8;
    int d4 = (idx4 & 255) * 4;
    int p0 = g_tok_pair[2 * t], p1 = g_tok_pair[2 * t + 1];
    int e0 = g_tok_e[2 * t], e1 = g_tok_e[2 * t + 1];
    float w0 = g_tok_w[2 * t], w1 = g_tok_w[2 * t + 1];
    float4 o0 = *(const float4*)(g_opair + (size_t)p0 * D + d4);
    float4 o1 = *(const float4*)(g_opair + (size_t)p1 * D + d4);
    float4 bb0 = *(const float4*)(b2 + (size_t)e0 * D + d4);
    float4 bb1 = *(const float4*)(b2 + (size_t)e1 * D + d4);
    float4 r;
    r.x = w0 * (o0.x + bb0.x) + w1 * (o1.x + bb1.x);
    r.y = w0 * (o0.y + bb0.y) + w1 * (o1.y + bb1.y);
    r.z = w0 * (o0.z + bb0.z) + w1 * (o1.z + bb1.z);
    r.w = w0 * (o0.w + bb0.w) + w1 * (o1.w + bb1.w);
    *(float4*)(out + (size_t)t * D + d4) = r;
}

// ---------------- launch ----------------
extern "C" void kernel_launch(void* const* d_in, const int* in_sizes, int n_in,
                              void* d_out, int out_size) {
    const float* x  = (const float*)d_in[0];
    const float* wg = (const float*)d_in[1];
    const float* W1 = (const float*)d_in[2];
    const float* b1 = (const float*)d_in[3];
    const float* W2 = (const float*)d_in[4];
    const float* b2 = (const float*)d_in[5];
    float* out = (float*)d_out;

    cudaFuncSetAttribute(mma_gemm_kernel<D, HDIM, true>,
                         cudaFuncAttributeMaxDynamicSharedMemorySize, SMEM_DYN);
    cudaFuncSetAttribute(mma_gemm_kernel<HDIM, D, false>,
                         cudaFuncAttributeMaxDynamicSharedMemorySize, SMEM_DYN);

    float* w1t; cudaGetSymbolAddress((void**)&w1t, g_w1t);
    float* w2t; cudaGetSymbolAddress((void**)&w2t, g_w2t);
    float* xa;  cudaGetSymbolAddress((void**)&xa, g_xa);
    float* gh;  cudaGetSymbolAddress((void**)&gh, g_h);
    float* gop; cudaGetSymbolAddress((void**)&gop, g_opair);

    init_kernel<<<1, 32>>>();
    // W1 [E][D][H] -> g_w1t [E][H][D];  W2 [E][H][D] -> g_w2t [E][D][H]
    transpose_round_kernel<<<dim3(HDIM / 32, D / 32, E), 256>>>(W1, w1t, D, HDIM);
    transpose_round_kernel<<<dim3(D / 32, HDIM / 32, E), 256>>>(W2, w2t, HDIM, D);
    router_kernel<<<T / 8, 256>>>(x, wg);
    setup_kernel<<<1, 256>>>(out, out_size);
    scatter_kernel<<<T / 256, 256>>>();
    gather_kernel<<<2 * T, 256>>>(x);
    mma_gemm_kernel<D, HDIM, true><<<dim3(HDIM / BN, MAXTILES), 256, SMEM_DYN>>>(xa, w1t, b1, gh);
    mma_gemm_kernel<HDIM, D, false><<<dim3(D / BN, MAXTILES), 256, SMEM_DYN>>>(gh, w2t, nullptr, gop);
    combine_kernel<<<(T * D / 4) / 256, 256>>>(b2, out);
}

// round 4
// speedup vs baseline: 5.1122x; 1.7092x over previous
#include <cuda_runtime.h>
#include <cuda_fp16.h>
#include <math.h>
#include <stdint.h>

#define T 4096
#define D 1024
#define HDIM 4096
#define E 8
#define BM 128
#define BN 128
#define BK 64                 // 64 halves = 128B rows
#define STAGES 4
#define STAGE_BYTES 32768     // A 16KB + B 16KB
#define SMEM_DYN (STAGES * STAGE_BYTES)
#define MAXTILES 72

// ---------------- scratch (device globals) ----------------
__device__ int    g_counts[E];
__device__ int    g_offsets[E];
__device__ int    g_cursor[E];
__device__ int    g_tok_e[2 * T];
__device__ float  g_tok_w[2 * T];
__device__ int    g_tok_pair[2 * T];
__device__ int    g_pair_token[2 * T];
__device__ float  g_probs[T * E];
__device__ int    g_tile_e[MAXTILES];
__device__ int    g_tile_m0[MAXTILES];
__device__ int    g_ntiles;
__device__ __half g_xa[(2 * T + 128) * D];                   // gathered x (fp16)
__device__ __half g_h[(size_t)(2 * T + 128) * HDIM];         // gelu output (fp16)
__device__ float  g_opair[(size_t)2 * T * D];                // gemm2 out (fp32)
__device__ __half g_w1t[(size_t)E * HDIM * D];               // W1^T fp16: [E][H][D]
__device__ __half g_w2t[(size_t)E * D * HDIM];               // W2^T fp16: [E][D][H]

// ---------------- PTX helpers ----------------
__device__ __forceinline__ uint32_t smem_u32(const void* p) {
    uint32_t a;
    asm("{ .reg .u64 t; cvta.to.shared.u64 t, %1; cvt.u32.u64 %0, t; }" : "=r"(a) : "l"(p));
    return a;
}

#define CP_ASYNC16(saddr, gptr) \
    asm volatile("cp.async.cg.shared.global [%0], [%1], 16;" :: "r"(saddr), "l"(gptr) : "memory")
#define CP_COMMIT() asm volatile("cp.async.commit_group;" ::: "memory")
#define CP_WAIT(n)  asm volatile("cp.async.wait_group %0;" :: "n"(n) : "memory")

#define LDSM_X4(r0, r1, r2, r3, addr) \
    asm volatile("ldmatrix.sync.aligned.m8n8.x4.shared.b16 {%0,%1,%2,%3}, [%4];" \
        : "=r"(r0), "=r"(r1), "=r"(r2), "=r"(r3) : "r"(addr))

#define MMA_F16(d, a, b0, b1) \
    asm volatile("mma.sync.aligned.m16n8k16.row.col.f32.f16.f16.f32 " \
        "{%0,%1,%2,%3}, {%4,%5,%6,%7}, {%8,%9}, {%0,%1,%2,%3};" \
        : "+f"((d)[0]), "+f"((d)[1]), "+f"((d)[2]), "+f"((d)[3]) \
        : "r"((a)[0]), "r"((a)[1]), "r"((a)[2]), "r"((a)[3]), "r"(b0), "r"(b1))

__device__ __forceinline__ uint32_t swz(uint32_t off) {
    return off ^ ((off >> 3) & 0x70);
}

__device__ __forceinline__ float gelu_tanh(float v) {
    float c = v + 0.044715f * v * v * v;
    return 0.5f * v * (1.0f + tanhf(0.7978845608028654f * c));
}

// ---------------- routing kernels ----------------
__global__ void init_kernel() {
    if (threadIdx.x < E) g_counts[threadIdx.x] = 0;
}

__global__ __launch_bounds__(256) void router_kernel(const float* __restrict__ x,
                                                     const float* __restrict__ wg) {
    __shared__ float ws[E * D];
    for (int i = threadIdx.x; i < E * D; i += 256) ws[i] = wg[i];
    __syncthreads();
    int warp = threadIdx.x >> 5, lane = threadIdx.x & 31;
    int t = blockIdx.x * 8 + warp;
    float p[E];
#pragma unroll
    for (int e = 0; e < E; e++) p[e] = 0.0f;
    const float* xr = x + (size_t)t * D;
    for (int i = lane; i < D; i += 32) {
        float xv = xr[i];
#pragma unroll
        for (int e = 0; e < E; e++) p[e] += xv * ws[e * D + i];
    }
#pragma unroll
    for (int e = 0; e < E; e++)
#pragma unroll
        for (int off = 16; off > 0; off >>= 1)
            p[e] += __shfl_down_sync(0xffffffffu, p[e], off);
    if (lane == 0) {
        float mx = p[0];
#pragma unroll
        for (int e = 1; e < E; e++) mx = fmaxf(mx, p[e]);
        float ex[E], s = 0.0f;
#pragma unroll
        for (int e = 0; e < E; e++) { ex[e] = expf(p[e] - mx); s += ex[e]; }
        float inv = 1.0f / s;
#pragma unroll
        for (int e = 0; e < E; e++) g_probs[t * E + e] = ex[e] * inv;
        int i0 = 0;
#pragma unroll
        for (int e = 1; e < E; e++) if (p[e] > p[i0]) i0 = e;
        int i1 = (i0 == 0) ? 1 : 0;
#pragma unroll
        for (int e = 0; e < E; e++) if (e != i0 && p[e] > p[i1]) i1 = e;
        float w0 = 1.0f / (1.0f + expf(p[i1] - p[i0]));
        g_tok_e[2 * t] = i0;  g_tok_e[2 * t + 1] = i1;
        g_tok_w[2 * t] = w0;  g_tok_w[2 * t + 1] = 1.0f - w0;
        atomicAdd(&g_counts[i0], 1);
        atomicAdd(&g_counts[i1], 1);
    }
}

__global__ __launch_bounds__(256) void setup_kernel(float* __restrict__ d_out, int out_size) {
    int tid = threadIdx.x;
    float gs[E], ps[E];
#pragma unroll
    for (int e = 0; e < E; e++) { gs[e] = 0.0f; ps[e] = 0.0f; }
    for (int t = tid; t < T; t += 256) {
        gs[g_tok_e[2 * t]]     += g_tok_w[2 * t];
        gs[g_tok_e[2 * t + 1]] += g_tok_w[2 * t + 1];
#pragma unroll
        for (int e = 0; e < E; e++) ps[e] += g_probs[t * E + e];
    }
    __shared__ float red[256];
    __shared__ float gsum[E], psum[E];
    for (int e = 0; e < E; e++) {
        red[tid] = gs[e]; __syncthreads();
        for (int s = 128; s > 0; s >>= 1) { if (tid < s) red[tid] += red[tid + s]; __syncthreads(); }
        if (tid == 0) gsum[e] = red[0];
        __syncthreads();
    }
    for (int e = 0; e < E; e++) {
        red[tid] = ps[e]; __syncthreads();
        for (int s = 128; s > 0; s >>= 1) { if (tid < s) red[tid] += red[tid + s]; __syncthreads(); }
        if (tid == 0) psum[e] = red[0];
        __syncthreads();
    }
    if (tid == 0) {
        float aux = 0.0f;
        for (int e = 0; e < E; e++) aux += (gsum[e] / (float)T) * (psum[e] / (float)T);
        aux *= (float)E;
        if (out_size > T * D) d_out[T * D] = aux;
        int off = 0, nt = 0;
        for (int e = 0; e < E; e++) {
            g_offsets[e] = off;
            for (int m0 = 0; m0 < g_counts[e]; m0 += BM) { g_tile_e[nt] = e; g_tile_m0[nt] = m0; nt++; }
            off += g_counts[e];
            g_cursor[e] = 0;
        }
        g_ntiles = nt;
    }
}

__global__ __launch_bounds__(256) void scatter_kernel() {
    int t = blockIdx.x * 256 + threadIdx.x;
    if (t >= T) return;
#pragma unroll
    for (int k = 0; k < 2; k++) {
        int e = g_tok_e[2 * t + k];
        int p = g_offsets[e] + atomicAdd(&g_cursor[e], 1);
        g_pair_token[p] = t;
        g_tok_pair[2 * t + k] = p;
    }
}

// gather x rows into pair order, convert to fp16
__global__ __launch_bounds__(256) void gather_kernel(const float* __restrict__ x) {
    int p = blockIdx.x;
    int tok = g_pair_token[p];
    int c = threadIdx.x * 4;
    float4 v = *(const float4*)(x + (size_t)tok * D + c);
    __half2 h0 = __floats2half2_rn(v.x, v.y);
    __half2 h1 = __floats2half2_rn(v.z, v.w);
    uint2 u;
    u.x = *reinterpret_cast<uint32_t*>(&h0);
    u.y = *reinterpret_cast<uint32_t*>(&h1);
    *reinterpret_cast<uint2*>(g_xa + (size_t)p * D + c) = u;
}

// transpose [K][N] -> [N][K] per expert, fp32 -> fp16
__global__ __launch_bounds__(256) void transpose_half_kernel(const float* __restrict__ src,
                                                             __half* __restrict__ dst,
                                                             int K, int N) {
    __shared__ float s[32][33];
    int e = blockIdx.z;
    src += (size_t)e * K * N;
    dst += (size_t)e * N * K;
    int k0 = blockIdx.y * 32, n0 = blockIdx.x * 32;
    int r = threadIdx.x >> 3;
    int c4 = (threadIdx.x & 7) * 4;
    float4 v = *(const float4*)(src + (size_t)(k0 + r) * N + n0 + c4);
    s[r][c4 + 0] = v.x;
    s[r][c4 + 1] = v.y;
    s[r][c4 + 2] = v.z;
    s[r][c4 + 3] = v.w;
    __syncthreads();
    __half2 h0 = __floats2half2_rn(s[c4 + 0][r], s[c4 + 1][r]);
    __half2 h1 = __floats2half2_rn(s[c4 + 2][r], s[c4 + 3][r]);
    uint2 u;
    u.x = *reinterpret_cast<uint32_t*>(&h0);
    u.y = *reinterpret_cast<uint32_t*>(&h1);
    *reinterpret_cast<uint2*>(dst + (size_t)(n0 + r) * K + k0 + c4) = u;
}

// ---------------- fp16 mma.sync grouped GEMM ----------------
// A: [pairs][KTOT] k-major fp16. Bt: [E][NTOT][KTOT] k-major fp16.
// CTA 128x128, BK=64 (128B rows), 4-stage cp.async, 8 warps (2m x 4n), warp 64x32.
// OutT: __half (GEMM1, gelu) or float (GEMM2).
template<int KTOT, int NTOT, bool GELU, typename OutT>
__global__ __launch_bounds__(256, 1) void mma_gemm_kernel(
    const __half* __restrict__ Aall, const __half* __restrict__ Bt,
    const float* __restrict__ bias, OutT* __restrict__ Out)
{
    int ty = blockIdx.y;
    if (ty >= g_ntiles) return;
    int e = g_tile_e[ty];
    int m0 = g_tile_m0[ty];
    int cnt = g_counts[e];
    int base = g_offsets[e];
    int n0 = blockIdx.x * BN;

    extern __shared__ char sm[];
    uint32_t sbase = smem_u32(sm);
    int tid = threadIdx.x;
    int wid = tid >> 5, lane = tid & 31;
    int warp_m = wid & 1, warp_n = wid >> 1;
    int m_base = warp_m * 64, n_base = warp_n * 32;

    const __half* Abase = Aall + (size_t)(base + m0) * KTOT;
    const __half* Bbase = Bt + ((size_t)e * NTOT + n0) * KTOT;

    float acc[4][4][4];
#pragma unroll
    for (int i = 0; i < 4; i++)
#pragma unroll
        for (int j = 0; j < 4; j++)
#pragma unroll
            for (int k = 0; k < 4; k++) acc[i][j][k] = 0.0f;

    const int KITERS = KTOT / BK;

#define LOAD_STAGE(s, it) do { \
        uint32_t a_sm_ = sbase + (uint32_t)(s) * STAGE_BYTES; \
        uint32_t b_sm_ = a_sm_ + 16384; \
        int k0_ = (it) * BK; \
        _Pragma("unroll") \
        for (int j_ = 0; j_ < 4; j_++) { \
            int chunk_ = tid + 256 * j_; \
            int row_ = chunk_ >> 3, cc_ = chunk_ & 7; \
            uint32_t off_ = (uint32_t)(row_ * 128 + cc_ * 16); \
            CP_ASYNC16(a_sm_ + swz(off_), Abase + (size_t)row_ * KTOT + k0_ + cc_ * 8); \
        } \
        _Pragma("unroll") \
        for (int j_ = 0; j_ < 4; j_++) { \
            int chunk_ = tid + 256 * j_; \
            int row_ = chunk_ >> 3, cc_ = chunk_ & 7; \
            uint32_t off_ = (uint32_t)(row_ * 128 + cc_ * 16); \
            CP_ASYNC16(b_sm_ + swz(off_), Bbase + (size_t)row_ * KTOT + k0_ + cc_ * 8); \
        } \
    } while (0)

    // prologue
#pragma unroll
    for (int s = 0; s < STAGES - 1; s++) {
        LOAD_STAGE(s, s);
        CP_COMMIT();
    }

    int lrow = lane & 15;
    uint32_t lkhi = (uint32_t)((lane >> 4) * 16);

    for (int it = 0; it < KITERS; ++it) {
        CP_WAIT(STAGES - 2);
        __syncthreads();

        int nxt = it + STAGES - 1;
        if (nxt < KITERS) LOAD_STAGE(nxt % STAGES, nxt);
        CP_COMMIT();

        uint32_t a_sm = sbase + (uint32_t)(it % STAGES) * STAGE_BYTES;
        uint32_t b_sm = a_sm + 16384;

#pragma unroll
        for (int ks = 0; ks < 4; ks++) {   // 4 x k16 per BK=64
            uint32_t a[4][4], b[2][4];
#pragma unroll
            for (int mt = 0; mt < 4; mt++) {
                uint32_t off = (uint32_t)((m_base + mt * 16 + lrow) * 128) + ks * 32 + lkhi;
                LDSM_X4(a[mt][0], a[mt][1], a[mt][2], a[mt][3], a_sm + swz(off));
            }
#pragma unroll
            for (int np = 0; np < 2; np++) {
                uint32_t off = (uint32_t)((n_base + np * 16 + lrow) * 128) + ks * 32 + lkhi;
                LDSM_X4(b[np][0], b[np][1], b[np][2], b[np][3], b_sm + swz(off));
            }
            // regs: a[mt] = m16k16 fragment; b[np] = {b0(n0-7), b0(n8-15), b1(n0-7), b1(n8-15)}
#pragma unroll
            for (int mt = 0; mt < 4; mt++)
#pragma unroll
                for (int nt = 0; nt < 4; nt++)
                    MMA_F16(acc[mt][nt], a[mt], b[nt >> 1][nt & 1], b[nt >> 1][(nt & 1) + 2]);
        }
    }

    // ---- epilogue ----
    int rq = lane >> 2;
    int cq = (lane & 3) * 2;
#pragma unroll
    for (int mt = 0; mt < 4; mt++) {
#pragma unroll
        for (int h = 0; h < 2; h++) {
            int row = m_base + mt * 16 + h * 8 + rq;
            int m = m0 + row;
            if (m >= cnt) continue;
            OutT* orow = Out + (size_t)(base + m) * NTOT + n0;
#pragma unroll
            for (int nt = 0; nt < 4; nt++) {
                int col = n_base + nt * 8 + cq;
                float v0 = acc[mt][nt][h * 2 + 0];
                float v1 = acc[mt][nt][h * 2 + 1];
                if (GELU) {
                    const float* bp = bias + (size_t)e * NTOT + n0 + col;
                    v0 = gelu_tanh(v0 + bp[0]);
                    v1 = gelu_tanh(v1 + bp[1]);
                }
                if (sizeof(OutT) == 2) {
                    __half2 hv = __floats2half2_rn(v0, v1);
                    *reinterpret_cast<__half2*>(orow + col) = hv;
                } else {
                    float2 st; st.x = v0; st.y = v1;
                    *reinterpret_cast<float2*>(orow + col) = st;
                }
            }
        }
    }
#undef LOAD_STAGE
}

// ---------------- combine ----------------
__global__ __launch_bounds__(256) void combine_kernel(const float* __restrict__ b2,
                                                      float* __restrict__ out) {
    int idx4 = blockIdx.x * 256 + threadIdx.x;
    int t = idx4 >> 8;
    int d4 = (idx4 & 255) * 4;
    int p0 = g_tok_pair[2 * t], p1 = g_tok_pair[2 * t + 1];
    int e0 = g_tok_e[2 * t], e1 = g_tok_e[2 * t + 1];
    float w0 = g_tok_w[2 * t], w1 = g_tok_w[2 * t + 1];
    float4 o0 = *(const float4*)(g_opair + (size_t)p0 * D + d4);
    float4 o1 = *(const float4*)(g_opair + (size_t)p1 * D + d4);
    float4 bb0 = *(const float4*)(b2 + (size_t)e0 * D + d4);
    float4 bb1 = *(const float4*)(b2 + (size_t)e1 * D + d4);
    float4 r;
    r.x = w0 * (o0.x + bb0.x) + w1 * (o1.x + bb1.x);
    r.y = w0 * (o0.y + bb0.y) + w1 * (o1.y + bb1.y);
    r.z = w0 * (o0.z + bb0.z) + w1 * (o1.z + bb1.z);
    r.w = w0 * (o0.w + bb0.w) + w1 * (o1.w + bb1.w);
    *(float4*)(out + (size_t)t * D + d4) = r;
}

// ---------------- launch ----------------
extern "C" void kernel_launch(void* const* d_in, const int* in_sizes, int n_in,
                              void* d_out, int out_size) {
    const float* x  = (const float*)d_in[0];
    const float* wg = (const float*)d_in[1];
    const float* W1 = (const float*)d_in[2];
    const float* b1 = (const float*)d_in[3];
    const float* W2 = (const float*)d_in[4];
    const float* b2 = (const float*)d_in[5];
    float* out = (float*)d_out;

    cudaFuncSetAttribute(mma_gemm_kernel<D, HDIM, true, __half>,
                         cudaFuncAttributeMaxDynamicSharedMemorySize, SMEM_DYN);
    cudaFuncSetAttribute(mma_gemm_kernel<HDIM, D, false, float>,
                         cudaFuncAttributeMaxDynamicSharedMemorySize, SMEM_DYN);

    __half* w1t; cudaGetSymbolAddress((void**)&w1t, g_w1t);
    __half* w2t; cudaGetSymbolAddress((void**)&w2t, g_w2t);
    __half* xa;  cudaGetSymbolAddress((void**)&xa, g_xa);
    __half* gh;  cudaGetSymbolAddress((void**)&gh, g_h);
    float* gop;  cudaGetSymbolAddress((void**)&gop, g_opair);

    init_kernel<<<1, 32>>>();
    // W1 [E][D][H] -> g_w1t [E][H][D];  W2 [E][H][D] -> g_w2t [E][D][H]
    transpose_half_kernel<<<dim3(HDIM / 32, D / 32, E), 256>>>(W1, w1t, D, HDIM);
    transpose_half_kernel<<<dim3(D / 32, HDIM / 32, E), 256>>>(W2, w2t, HDIM, D);
    router_kernel<<<T / 8, 256>>>(x, wg);
    setup_kernel<<<1, 256>>>(out, out_size);
    scatter_kernel<<<T / 256, 256>>>();
    gather_kernel<<<2 * T, 256>>>(x);
    mma_gemm_kernel<D, HDIM, true, __half><<<dim3(HDIM / BN, MAXTILES), 256, SMEM_DYN>>>(xa, w1t, b1, gh);
    mma_gemm_kernel<HDIM, D, false, float><<<dim3(D / BN, MAXTILES), 256, SMEM_DYN>>>(gh, w2t, nullptr, gop);
    combine_kernel<<<(T * D / 4) / 256, 256>>>(b2, out);
}